// round 15
// baseline (speedup 1.0000x reference)
#include <cuda_runtime.h>

#define NB 64
#define SEQLEN 512
#define HIDN 512
#define PROJ 128
#define NGATE 2048
#define G 8        // CTAs per cluster/group
#define NGRP 16    // clusters (16*8 = 128 CTAs, 4 batches per group)
typedef unsigned long long ull;

// ---------------- device scratch (no runtime allocation allowed) ------------
__device__ __align__(16) float g_A[NGATE * 16];
__device__ __align__(16) float g_cbias[NGATE];
__device__ __align__(16) float g_cbase[NGATE * NB];                 // [r][b]
__device__ __align__(16) float g_xg2[(size_t)SEQLEN * 128 * 1024];  // [t][ci][rr*4+b']
__device__ __align__(16) float g_hs[(size_t)SEQLEN * PROJ * NB];    // [t][p][b]

// ---------------- helpers ---------------------------------------------------
static __device__ __forceinline__ ull pk2(float x, float y) {
    ull r; asm("mov.b64 %0, {%1,%2};" : "=l"(r) : "f"(x), "f"(y)); return r;
}
static __device__ __forceinline__ void upk2(ull v, float& x, float& y) {
    asm("mov.b64 {%0,%1}, %2;" : "=f"(x), "=f"(y) : "l"(v));
}
static __device__ __forceinline__ ull ffma2(ull a, ull b, ull c) {
    ull d; asm("fma.rn.f32x2 %0, %1, %2, %3;" : "=l"(d) : "l"(a), "l"(b), "l"(c));
    return d;
}
static __device__ __forceinline__ ull addx2(ull a, ull b) {
    ull d; asm("add.rn.f32x2 %0, %1, %2;" : "=l"(d) : "l"(a), "l"(b));
    return d;
}
static __device__ __forceinline__ float sigf(float x) {
    return __fdividef(1.f, 1.f + __expf(-x));
}
static __device__ __forceinline__ float tanh_fast(float x) {
    return 1.f - __fdividef(2.f, __expf(2.f * x) + 1.f);
}
static __device__ __forceinline__ unsigned smem_u32(const void* p) {
    unsigned a;
    asm("{ .reg .u64 t; cvta.to.shared.u64 t, %1; cvt.u32.u64 %0, t; }"
        : "=r"(a) : "l"(p));
    return a;
}
// DSMEM b64 store to the same smem offset in cluster CTA `rank`
static __device__ __forceinline__ void st_dsm_b64(unsigned laddr, int rank, ull v) {
    unsigned ra;
    asm volatile("mapa.shared::cluster.u32 %0, %1, %2;" : "=r"(ra) : "r"(laddr), "r"(rank));
    asm volatile("st.shared::cluster.b64 [%0], %1;" :: "r"(ra), "l"(v) : "memory");
}
#define CARRIVE() asm volatile("barrier.cluster.arrive.aligned;" ::: "memory")
#define CWAIT()   asm volatile("barrier.cluster.wait.aligned;" ::: "memory")

// ============================================================================
// S1: A[r][0..13], cbias[r]. 64 blocks x 1024 thr; one warp per gate row.
// ============================================================================
__global__ void k_setup1(const float* __restrict__ Wih,
                         const float* __restrict__ cmdW, const float* __restrict__ cmdb,
                         const float* __restrict__ coordW, const float* __restrict__ coordb,
                         const float* __restrict__ bih, const float* __restrict__ bhh) {
    int r = blockIdx.x * 32 + (threadIdx.x >> 5);
    int lane = threadIdx.x & 31;
    float acc[15];
#pragma unroll
    for (int j = 0; j < 15; j++) acc[j] = 0.f;
    for (int k = lane; k < HIDN; k += 32) {
        float w = Wih[(size_t)r * 768 + k];
#pragma unroll
        for (int j = 0; j < 6; j++) acc[j] += w * cmdW[k * 6 + j];
#pragma unroll
        for (int j = 0; j < 8; j++) acc[6 + j] += w * coordW[k * 8 + j];
        acc[14] += w * (cmdb[k] + coordb[k]);
    }
#pragma unroll
    for (int j = 0; j < 15; j++)
#pragma unroll
        for (int off = 16; off; off >>= 1)
            acc[j] += __shfl_down_sync(0xffffffffu, acc[j], off);
    if (lane == 0) {
#pragma unroll
        for (int j = 0; j < 14; j++) g_A[r * 16 + j] = acc[j];
        g_A[r * 16 + 14] = 0.f;
        g_A[r * 16 + 15] = 0.f;
        g_cbias[r] = acc[14] + bih[r] + bhh[r];
    }
}

// ============================================================================
// S2: cbase[r][b] = cbias[r] + W_ih_ctx[r]·ctx[b]. 16 blocks x 256.
// ============================================================================
__global__ void k_setup2(const float* __restrict__ Wih, const float* __restrict__ ctx) {
    __shared__ float sC[1024];
    int tid = threadIdx.x;
    int bs = blockIdx.x * 4;
    for (int i = tid; i < 1024; i += 256) sC[i] = ctx[(size_t)bs * 256 + i];
    __syncthreads();
    for (int r = tid; r < NGATE; r += 256) {
        float a0 = 0.f, a1 = 0.f, a2 = 0.f, a3 = 0.f;
        const float* wr = Wih + (size_t)r * 768 + 512;
        for (int l = 0; l < 256; l++) {
            float w = wr[l];
            a0 += w * sC[l]; a1 += w * sC[256 + l];
            a2 += w * sC[512 + l]; a3 += w * sC[768 + l];
        }
        float cb = g_cbias[r];
        g_cbase[r * 64 + bs + 0] = a0 + cb;
        g_cbase[r * 64 + bs + 1] = a1 + cb;
        g_cbase[r * 64 + bs + 2] = a2 + cb;
        g_cbase[r * 64 + bs + 3] = a3 + cb;
    }
}

// ============================================================================
// XG: x_gates into per-CTA blocks: g_xg2[t][ci][(q*64+ul)*4 + b'].
// ============================================================================
__global__ void k_xg(const float* __restrict__ x) {
    __shared__ float xs[64 * 16];
    int t = blockIdx.x;
    int rbase = blockIdx.y * 64;
    int tid = threadIdx.x;
    for (int i = tid; i < 64 * 14; i += 256) {
        int b = i / 14, j = i % 14;
        xs[b * 16 + j] = x[((size_t)b * SEQLEN + t) * 14 + j];
    }
    __syncthreads();
    int rl = tid >> 2, bq = tid & 3;
    int r = rbase + rl;
    const float* Ar = g_A + r * 16;
    float a[14];
#pragma unroll
    for (int j = 0; j < 14; j++) a[j] = Ar[j];
    const float* cb = g_cbase + r * 64 + bq * 16;
    int qq = r >> 9, cgx = (r >> 6) & 7, ul = r & 63;
    int rr = qq * 64 + ul;
#pragma unroll
    for (int q = 0; q < 4; q++) {
        float4 res;
        float* rp = (float*)&res;
#pragma unroll
        for (int e = 0; e < 4; e++) {
            int b = bq * 16 + q * 4 + e;
            float acc = cb[q * 4 + e];
            const float* xr = xs + b * 16;
#pragma unroll
            for (int j = 0; j < 14; j++) acc += a[j] * xr[j];
            rp[e] = acc;
        }
        int gr = bq * 4 + q;
        float4* outp = (float4*)(g_xg2 + (((size_t)t * 128 + gr * 8 + cgx) * 1024)) + rr;
        *outp = res;
    }
}

// ============================================================================
// REC: 16 clusters x 8 CTAs x 4 batches; DSMEM exchange + cluster barriers.
// Dyn smem 179712 B (floats): sW 32768 | sWhr 8320 | sH 512 | sGate 1024 |
// sZ 2048 | sRed 256.
// ============================================================================
__global__ void __launch_bounds__(128, 1) __cluster_dims__(G, 1, 1)
k_rec(const float* __restrict__ Whh, const float* __restrict__ Whr) {
    extern __shared__ float sm[];
    float* sW    = sm;                 // [k128][rr256]
    float* sWhr  = sm + 32768;         // [pl16][520]
    float* sH    = sm + 41088;         // [p128][b4]   (peer-written)
    float* sGate = sm + 41600;         // [rr256][b4]
    float* sZ    = sm + 42624;         // [k512][b4]   (peer-written)
    float* sRed  = sm + 44672;         // 128 ull
    const int tid = threadIdx.x;
    const int ci = blockIdx.x;
    const int gr = ci >> 3;
    const int cg = ci & 7;                  // cluster rank
    const unsigned hb = smem_u32(sH);
    const unsigned zb = smem_u32(sZ);

    // W_hh shard: 256 gate rows (q*512 + cg*64 + ul), k-major
    for (int i = tid; i < 32768; i += 128) {
        int rr = i >> 7, k = i & 127;
        int rglob = (rr >> 6) * 512 + cg * 64 + (rr & 63);
        sW[k * 256 + rr] = Whh[(size_t)rglob * 128 + k];
    }
    // W_hr shard: 16 p-rows, padded stride 520
    for (int i = tid; i < 16 * 512; i += 128) {
        int pl = i >> 9, k = i & 511;
        sWhr[pl * 520 + k] = Whr[(size_t)(cg * 16 + pl) * 512 + k];
    }
    // h0 = 0 (own copy; peers update it via DSMEM after barriers)
    for (int i = tid; i < 512; i += 128) sH[i] = 0.f;

    const int u1 = tid >> 1;                // cell unit row (local 0..63)
    const int bsl = (tid & 1) * 2;          // batch pair 0 or 2
    const int pl = tid >> 3, bp = (tid >> 2) & 1, kq = tid & 3;  // phase B map
    float c0 = 0.f, c1 = 0.f;
    __syncthreads();

    // prefetch xg(0)
    const float4* xp0 = (const float4*)(g_xg2 + ((size_t)0 * 128 + ci) * 1024) + 2 * tid;
    float4 xg0 = __ldcg(xp0);
    float4 xg1 = __ldcg(xp0 + 1);

    for (int t = 0; t < SEQLEN; t++) {
        // ---- phase A: gates for rows 2tid, 2tid+1, K=128 from local sH ----
        ull a00 = 0, a01 = 0, a10 = 0, a11 = 0;
        {
            const float* wbase = sW + 2 * tid;
#pragma unroll 4
            for (int k = 0; k < 128; k++) {
                float2 w = *(const float2*)(wbase + k * 256);
                ulonglong2 hv = *(const ulonglong2*)(sH + k * 4);
                ull w0 = pk2(w.x, w.x), w1 = pk2(w.y, w.y);
                a00 = ffma2(w0, hv.x, a00); a01 = ffma2(w0, hv.y, a01);
                a10 = ffma2(w1, hv.x, a10); a11 = ffma2(w1, hv.y, a11);
            }
        }
        a00 = addx2(a00, pk2(xg0.x, xg0.y)); a01 = addx2(a01, pk2(xg0.z, xg0.w));
        a10 = addx2(a10, pk2(xg1.x, xg1.y)); a11 = addx2(a11, pk2(xg1.z, xg1.w));
        // gate exchange within CTA
        {
            float4 v0, v1;
            upk2(a00, v0.x, v0.y); upk2(a01, v0.z, v0.w);
            upk2(a10, v1.x, v1.y); upk2(a11, v1.z, v1.w);
            ((float4*)sGate)[2 * tid] = v0;
            ((float4*)sGate)[2 * tid + 1] = v1;
        }
        __syncthreads();
        // ---- cell update: unit u1, batches bsl, bsl+1 ----
        {
            float i0 = sigf(sGate[u1 * 4 + bsl]);
            float f0 = sigf(sGate[(64 + u1) * 4 + bsl]);
            float gg0 = tanh_fast(sGate[(128 + u1) * 4 + bsl]);
            float o0 = sigf(sGate[(192 + u1) * 4 + bsl]);
            c0 = f0 * c0 + i0 * gg0;
            float z0 = o0 * tanh_fast(c0);
            float i1 = sigf(sGate[u1 * 4 + bsl + 1]);
            float f1 = sigf(sGate[(64 + u1) * 4 + bsl + 1]);
            float gg1 = tanh_fast(sGate[(128 + u1) * 4 + bsl + 1]);
            float o1 = sigf(sGate[(192 + u1) * 4 + bsl + 1]);
            c1 = f1 * c1 + i1 * gg1;
            float z1 = o1 * tanh_fast(c1);
            // publish z(k = cg*64+u1, b = bsl..bsl+1) to all 8 CTAs' sZ
            ull zv = pk2(z0, z1);
            unsigned la = zb + ((cg * 64 + u1) * 4 + bsl) * 4;
#pragma unroll
            for (int r = 0; r < G; r++) st_dsm_b64(la, r, zv);
        }
        CARRIVE();
        // overlap: prefetch xg(t+1) (DRAM) under the barrier wait
        {
            int tn = (t + 1 < SEQLEN) ? t + 1 : t;
            const float4* xp = (const float4*)(g_xg2 + ((size_t)tn * 128 + ci) * 1024) + 2 * tid;
            xg0 = __ldcg(xp);
            xg1 = __ldcg(xp + 1);
        }
        CWAIT();

        // ---- phase B: h(p = cg*16+pl) partial over k = kq + 4j ----
        ull acc = 0ull;
        {
            const float* wrow = sWhr + pl * 520 + kq;
            const float* zcol = sZ + kq * 4 + bp * 2;
#pragma unroll 4
            for (int j = 0; j < 128; j++) {
                float w = wrow[j * 4];
                float2 zv = *(const float2*)(zcol + j * 16);
                acc = ffma2(pk2(w, w), pk2(zv.x, zv.y), acc);
            }
        }
        ((ull*)sRed)[tid] = acc;
        __syncthreads();
        if (tid < 32) {
            int pl2 = tid >> 1, bp2 = tid & 1;
            const ull* rp = (const ull*)sRed + pl2 * 8 + bp2 * 4;
            float x0, y0, x1, y1, x2, y2, x3, y3;
            upk2(rp[0], x0, y0); upk2(rp[1], x1, y1);
            upk2(rp[2], x2, y2); upk2(rp[3], x3, y3);
            float h0 = x0 + x1 + x2 + x3, h1 = y0 + y1 + y2 + y3;
            int p = cg * 16 + pl2;
            // publish h to all 8 CTAs' sH
            ull hv = pk2(h0, h1);
            unsigned la = hb + (p * 4 + bp2 * 2) * 4;
#pragma unroll
            for (int r = 0; r < G; r++) st_dsm_b64(la, r, hv);
            // record hs for the head kernel (global; consumed post-kernel)
            *(float2*)(g_hs + ((size_t)t * PROJ + p) * 64 + gr * 4 + bp2 * 2) =
                make_float2(h0, h1);
        }
        CARRIVE();
        CWAIT();
    }
}

// ============================================================================
// HEAD: LayerNorm + two output heads. 512 blocks (per t) x 64 thr (per b).
// ============================================================================
__global__ void k_head(const float* __restrict__ lng, const float* __restrict__ lnb,
                       const float* __restrict__ ocW, const float* __restrict__ ocb,
                       const float* __restrict__ oxW, const float* __restrict__ oxb,
                       const float* __restrict__ cscale, float* __restrict__ out) {
    __shared__ float sy[8192];
    __shared__ float s_ocW[768], s_oxW[804], s_lng[128], s_lnb[128], s_ocb[6], s_oxb[6], s_sc;
    int t = blockIdx.x, tid = threadIdx.x;
    {
        const float4* src = (const float4*)(g_hs + (size_t)t * 8192);
        float4* dst = (float4*)sy;
#pragma unroll
        for (int i = 0; i < 32; i++) dst[tid + i * 64] = src[tid + i * 64];
    }
    for (int i = tid; i < 768; i += 64) s_ocW[i] = ocW[i];
    for (int i = tid; i < 804; i += 64) s_oxW[i] = oxW[i];
    for (int i = tid; i < 128; i += 64) { s_lng[i] = lng[i]; s_lnb[i] = lnb[i]; }
    if (tid < 6) { s_ocb[tid] = ocb[tid]; s_oxb[tid] = oxb[tid]; }
    if (tid == 0) s_sc = cscale[0];
    __syncthreads();
    int b = tid;
    float sum = 0.f, sq = 0.f;
    for (int p = 0; p < 128; p++) { float v = sy[p * 64 + b]; sum += v; sq += v * v; }
    float mu = sum * (1.f / 128.f);
    float var = sq * (1.f / 128.f) - mu * mu;
    float rs = rsqrtf(var + 1e-5f);
    float cl[6], cx[6];
#pragma unroll
    for (int j = 0; j < 6; j++) { cl[j] = s_ocb[j]; cx[j] = s_oxb[j]; }
    for (int p = 0; p < 128; p++) {
        float y = (sy[p * 64 + b] - mu) * rs * s_lng[p] + s_lnb[p];
#pragma unroll
        for (int j = 0; j < 6; j++) cl[j] += y * s_ocW[j * 128 + p];
#pragma unroll
        for (int j = 0; j < 6; j++) cx[j] += y * s_oxW[j * 134 + p];
    }
#pragma unroll
    for (int j = 0; j < 6; j++)
#pragma unroll
        for (int m = 0; m < 6; m++) cx[j] += cl[m] * s_oxW[j * 134 + 128 + m];
    size_t o1 = ((size_t)b * SEQLEN + t) * 6;
#pragma unroll
    for (int j = 0; j < 6; j++) {
        out[o1 + j] = cl[j];
        out[196608 + o1 + j] = tanh_fast(cx[j] * s_sc);
    }
}

// ============================================================================
extern "C" void kernel_launch(void* const* d_in, const int* in_sizes, int n_in,
                              void* d_out, int out_size) {
    const float* x      = (const float*)d_in[0];
    const float* ctx    = (const float*)d_in[1];
    const float* cmdW   = (const float*)d_in[2];
    const float* cmdb   = (const float*)d_in[3];
    const float* coordW = (const float*)d_in[4];
    const float* coordb = (const float*)d_in[5];
    const float* Wih    = (const float*)d_in[6];
    const float* Whh    = (const float*)d_in[7];
    const float* bih    = (const float*)d_in[8];
    const float* bhh    = (const float*)d_in[9];
    const float* Whr    = (const float*)d_in[10];
    const float* lng    = (const float*)d_in[11];
    const float* lnb    = (const float*)d_in[12];
    const float* ocW    = (const float*)d_in[13];
    const float* ocb    = (const float*)d_in[14];
    const float* oxW    = (const float*)d_in[15];
    const float* oxb    = (const float*)d_in[16];
    const float* csc    = (const float*)d_in[17];
    float* out = (float*)d_out;

    // Unconditional, idempotent, capture-safe (not a stream op).
    cudaFuncSetAttribute(k_rec, cudaFuncAttributeMaxDynamicSharedMemorySize, 179712);

    k_setup1<<<64, 1024>>>(Wih, cmdW, cmdb, coordW, coordb, bih, bhh);
    k_setup2<<<16, 256>>>(Wih, ctx);
    k_xg<<<dim3(512, 32), 256>>>(x);
    k_rec<<<128, 128, 179712>>>(Whh, Whr);
    k_head<<<512, 64>>>(lng, lnb, ocW, ocb, oxW, oxb, csc, out);
}